// round 12
// baseline (speedup 1.0000x reference)
#include <cuda_runtime.h>
#include <cuda_bf16.h>
#include <cstdint>

// ---------------------------------------------------------------------------
// GIN encoder: 3 x (GINConv(sum-agg) -> MLP(64,relu,64) -> relu -> BN) -> add-pool
// Round 12 (base: round-11, 262us). Fuse gather + MLP into one k_layer:
//   * round-11 k_mlp was GRID-limited (391 blocks / 148 SMs -> occ 31%);
//     fused grid = 1563 blocks -> 3 blocks/SM (24 warps), and gather-phase /
//     MMA-phase blocks overlap (BW-bound + latency-bound mix per SM)
//   * deletes g_aggP round-trip (50MB/layer) + cp.async stage + 3 launches
//   * gather: 1 warp / 8 nodes, fp32 float2, ELL cols via coalesced load +
//     shfl, prev-layer BN affine folded in, bf16split -> P smem direct
//   * MMA: uint2-packed bf16x3 m16n8k16, W1+W2 staged per block
//   * BN stats: register accum -> smem -> global; sorted-batch pool
// ---------------------------------------------------------------------------

#define MAXN 131072
#define ELLW 64
#define KP2  36                 // smem pitch in uint2 words

__device__ int   g_cursor[MAXN];
__device__ int   g_ell[(size_t)MAXN * ELLW];
__device__ float g_rA[(size_t)MAXN * 64];
__device__ float g_rB[(size_t)MAXN * 64];
__device__ float g_stats[3 * 128];   // per layer: [0:64) sum, [64:128) sumsq
__device__ float g_coef[3 * 128];    // per layer: [0:64) scale a, [64:128) shift b

// split (ev,od) floats into packed-bf16 hi word (ev low half) + lo word
__device__ __forceinline__ void bf16split2(float ev, float od,
                                           uint32_t& hi, uint32_t& lo) {
    __nv_bfloat16 he = __float2bfloat16_rn(ev);
    __nv_bfloat16 ho = __float2bfloat16_rn(od);
    float le = ev - __bfloat162float(he);
    float lo_f = od - __bfloat162float(ho);
    __nv_bfloat162 ph, pl;
    ph.x = he; ph.y = ho;
    pl.x = __float2bfloat16_rn(le); pl.y = __float2bfloat16_rn(lo_f);
    hi = *(uint32_t*)&ph;
    lo = *(uint32_t*)&pl;
}

__device__ __forceinline__ void mma_bf16(float c[4],
    uint32_t a0, uint32_t a1, uint32_t a2, uint32_t a3,
    uint32_t b0, uint32_t b1)
{
    asm volatile(
        "mma.sync.aligned.m16n8k16.row.col.f32.bf16.bf16.f32 "
        "{%0,%1,%2,%3}, {%4,%5,%6,%7}, {%8,%9}, {%0,%1,%2,%3};"
        : "+f"(c[0]), "+f"(c[1]), "+f"(c[2]), "+f"(c[3])
        : "r"(a0), "r"(a1), "r"(a2), "r"(a3), "r"(b0), "r"(b1));
}

// ---------------------------- build ----------------------------------------

__global__ void k_zero(int N) {
    int i = blockIdx.x * blockDim.x + threadIdx.x;
    if (i < N)   g_cursor[i] = 0;
    if (i < 384) g_stats[i]  = 0.f;
}

__global__ void k_fill(const int* __restrict__ src, const int* __restrict__ dst, int E) {
    int e = blockIdx.x * blockDim.x + threadIdx.x;
    if (e < E) {
        int d = dst[e];
        int p = atomicAdd(&g_cursor[d], 1);
        if (p < ELLW) g_ell[(size_t)d * ELLW + p] = src[e];
    }
}

// ---------------- fused gather + bf16x3 tensor-core MLP ---------------------
// 256 threads (8 warps), 64-node tile per block. Warp tile m16 x n32.
// dyn smem: Q1[64][KP2] (W1, [n][kp]), Q2[64][KP2] (W2), P[64][KP2] (A / h).
__global__ __launch_bounds__(256) void k_layer(
    const float* __restrict__ x, int insel /*0=x,1=rA,2=rB*/, int layer,
    const float* __restrict__ wa, const float* __restrict__ ba,
    const float* __restrict__ wb, const float* __restrict__ bb,
    int outsel /*1=rA,2=rB*/, int N)
{
    extern __shared__ uint2 dyn[];
    uint2* Q1 = dyn;
    uint2* Q2 = dyn + 64 * KP2;
    uint2* P  = dyn + 2 * 64 * KP2;
    __shared__ float B1s[64], B2s[64];
    __shared__ float ssum[64], ssq[64];

    float* rout = (outsel == 1) ? g_rA : g_rB;
    int t    = threadIdx.x;
    int lane = t & 31, warp = t >> 5;
    int gid  = lane >> 2, tig = lane & 3;
    int mi   = warp & 3,  ni  = warp >> 2;
    int m0   = blockIdx.x * 64;

    // stage W1 + W2 (gather does not touch Q1/Q2; one sync covers all)
#pragma unroll
    for (int i = 0; i < 8; i++) {
        int idx = t + 256 * i;        // 0..2047
        int n = idx & 63, kp = idx >> 6;
        uint32_t hi, lo;
        bf16split2(wa[(2 * kp) * 64 + n], wa[(2 * kp + 1) * 64 + n], hi, lo);
        Q1[n * KP2 + kp] = make_uint2(hi, lo);
        bf16split2(wb[(2 * kp) * 64 + n], wb[(2 * kp + 1) * 64 + n], hi, lo);
        Q2[n * KP2 + kp] = make_uint2(hi, lo);
    }
    if (t < 64) { B1s[t] = ba[t]; B2s[t] = bb[t]; ssum[t] = 0.f; ssq[t] = 0.f; }

    // ---- gather phase: warp handles rows warp*8 .. warp*8+7 ----
    const float2* __restrict__ inp =
        (insel == 0) ? (const float2*)x :
        (insel == 1) ? (const float2*)g_rA : (const float2*)g_rB;

    float a0c = 1.f, a1c = 1.f, b0c = 0.f, b1c = 0.f;
    if (layer > 0) {
        const float* cf = &g_coef[(layer - 1) * 128];
        a0c = cf[2 * lane];      a1c = cf[2 * lane + 1];
        b0c = cf[64 + 2 * lane]; b1c = cf[65 + 2 * lane];
    }

#pragma unroll 1
    for (int i = 0; i < 8; i++) {
        int row  = warp * 8 + i;
        int node = m0 + row;
        float2 acc = make_float2(0.f, 0.f);
        if (node < N) {
            acc = inp[(size_t)node * 32 + lane];   // self term
            int deg = min(g_cursor[node], ELLW);
            const int* cols = g_ell + (size_t)node * ELLW;
            int c0 = cols[lane];
            int c1 = cols[lane + 32];

            int d0 = min(deg, 32);
            int e = 0;
            for (; e + 3 < d0; e += 4) {
                int s0 = __shfl_sync(0xffffffffu, c0, e);
                int s1 = __shfl_sync(0xffffffffu, c0, e + 1);
                int s2 = __shfl_sync(0xffffffffu, c0, e + 2);
                int s3 = __shfl_sync(0xffffffffu, c0, e + 3);
                float2 v0 = inp[(size_t)s0 * 32 + lane];
                float2 v1 = inp[(size_t)s1 * 32 + lane];
                float2 v2 = inp[(size_t)s2 * 32 + lane];
                float2 v3 = inp[(size_t)s3 * 32 + lane];
                acc.x += (v0.x + v1.x) + (v2.x + v3.x);
                acc.y += (v0.y + v1.y) + (v2.y + v3.y);
            }
            for (; e < d0; e++) {
                int s = __shfl_sync(0xffffffffu, c0, e);
                float2 v = inp[(size_t)s * 32 + lane];
                acc.x += v.x;
                acc.y += v.y;
            }
            int d1 = deg - 32;
            for (int e2 = 0; e2 < d1; e2++) {
                int s = __shfl_sync(0xffffffffu, c1, e2);
                float2 v = inp[(size_t)s * 32 + lane];
                acc.x += v.x;
                acc.y += v.y;
            }
            if (layer > 0) {
                float cnt = (float)(deg + 1);
                acc.x = a0c * acc.x + cnt * b0c;
                acc.y = a1c * acc.y + cnt * b1c;
            }
        }
        uint32_t hi, lo;
        bf16split2(acc.x, acc.y, hi, lo);
        P[row * KP2 + lane] = make_uint2(hi, lo);
    }
    __syncthreads();

    // ---- MMA phase ----
    int aoff = (mi * 16 + gid) * KP2 + tig;
    int boff = (ni * 32 + gid) * KP2 + tig;

    float c[4][4];
#pragma unroll
    for (int nt = 0; nt < 4; nt++)
#pragma unroll
        for (int i = 0; i < 4; i++) c[nt][i] = 0.f;

    // GEMM1
#pragma unroll
    for (int kt = 0; kt < 4; kt++) {
        uint2 a0 = P[aoff + kt * 8];
        uint2 a1 = P[aoff + kt * 8 + 8 * KP2];
        uint2 a2 = P[aoff + kt * 8 + 4];
        uint2 a3 = P[aoff + kt * 8 + 8 * KP2 + 4];
#pragma unroll
        for (int nt = 0; nt < 4; nt++) {
            uint2 b0 = Q1[boff + nt * 8 * KP2 + kt * 8];
            uint2 b1 = Q1[boff + nt * 8 * KP2 + kt * 8 + 4];
            mma_bf16(c[nt], a0.x, a1.x, a2.x, a3.x, b0.x, b1.x);
            mma_bf16(c[nt], a0.x, a1.x, a2.x, a3.x, b0.y, b1.y);
            mma_bf16(c[nt], a0.y, a1.y, a2.y, a3.y, b0.x, b1.x);
        }
    }
    __syncthreads();   // all P reads (A) done

    // h = relu(c + b1) -> P
#pragma unroll
    for (int nt = 0; nt < 4; nt++) {
        int n0 = ni * 32 + nt * 8 + 2 * tig;
        float bb0 = B1s[n0], bb1 = B1s[n0 + 1];
        int r0 = mi * 16 + gid;
        int kp = n0 >> 1;
        uint32_t hi, lo;
        bf16split2(fmaxf(c[nt][0] + bb0, 0.f), fmaxf(c[nt][1] + bb1, 0.f), hi, lo);
        P[r0 * KP2 + kp] = make_uint2(hi, lo);
        bf16split2(fmaxf(c[nt][2] + bb0, 0.f), fmaxf(c[nt][3] + bb1, 0.f), hi, lo);
        P[(r0 + 8) * KP2 + kp] = make_uint2(hi, lo);
#pragma unroll
        for (int i = 0; i < 4; i++) c[nt][i] = 0.f;
    }
    __syncthreads();

    // GEMM2
#pragma unroll
    for (int kt = 0; kt < 4; kt++) {
        uint2 a0 = P[aoff + kt * 8];
        uint2 a1 = P[aoff + kt * 8 + 8 * KP2];
        uint2 a2 = P[aoff + kt * 8 + 4];
        uint2 a3 = P[aoff + kt * 8 + 8 * KP2 + 4];
#pragma unroll
        for (int nt = 0; nt < 4; nt++) {
            uint2 b0 = Q2[boff + nt * 8 * KP2 + kt * 8];
            uint2 b1 = Q2[boff + nt * 8 * KP2 + kt * 8 + 4];
            mma_bf16(c[nt], a0.x, a1.x, a2.x, a3.x, b0.x, b1.x);
            mma_bf16(c[nt], a0.x, a1.x, a2.x, a3.x, b0.y, b1.y);
            mma_bf16(c[nt], a0.y, a1.y, a2.y, a3.y, b0.x, b1.x);
        }
    }

    // epilogue: relu + bias2, store fp32, BN stats -> smem -> global
    int gr0 = m0 + mi * 16 + gid, gr1 = gr0 + 8;
    bool ok0 = gr0 < N, ok1 = gr1 < N;
#pragma unroll
    for (int nt = 0; nt < 4; nt++) {
        int n0 = ni * 32 + nt * 8 + 2 * tig;
        float bb0 = B2s[n0], bb1 = B2s[n0 + 1];
        float v00 = fmaxf(c[nt][0] + bb0, 0.f);
        float v01 = fmaxf(c[nt][1] + bb1, 0.f);
        float v10 = fmaxf(c[nt][2] + bb0, 0.f);
        float v11 = fmaxf(c[nt][3] + bb1, 0.f);
        float s0 = 0.f, q0 = 0.f, s1 = 0.f, q1 = 0.f;
        if (ok0) {
            *(float2*)&rout[(size_t)gr0 * 64 + n0] = make_float2(v00, v01);
            s0 += v00; q0 += v00 * v00;
            s1 += v01; q1 += v01 * v01;
        }
        if (ok1) {
            *(float2*)&rout[(size_t)gr1 * 64 + n0] = make_float2(v10, v11);
            s0 += v10; q0 += v10 * v10;
            s1 += v11; q1 += v11 * v11;
        }
        atomicAdd(&ssum[n0],     s0);
        atomicAdd(&ssq[n0],      q0);
        atomicAdd(&ssum[n0 + 1], s1);
        atomicAdd(&ssq[n0 + 1],  q1);
    }
    __syncthreads();
    if (t < 64) {
        atomicAdd(&g_stats[layer * 128 + t],      ssum[t]);
        atomicAdd(&g_stats[layer * 128 + 64 + t], ssq[t]);
    }
}

// ---------------------------- BN finalize -----------------------------------
__global__ void k_bnfin(const float* __restrict__ gamma,
                        const float* __restrict__ beta, int layer, int N) {
    int t = threadIdx.x;  // 64
    if (t >= 64) return;
    float invN = 1.f / (float)N;
    float mean = g_stats[layer * 128 + t] * invN;
    float var  = g_stats[layer * 128 + 64 + t] * invN - mean * mean;
    var = fmaxf(var, 0.f);
    float s = gamma[t] * rsqrtf(var + 1e-5f);
    g_coef[layer * 128 + t]      = s;
    g_coef[layer * 128 + 64 + t] = beta[t] - mean * s;
}

// ---------------------------- pool ------------------------------------------
// batch sorted: run-length accumulate, atomics only at graph boundaries.
__global__ void k_pool(int insel /*1=rA,2=rB*/, const int* __restrict__ batch,
                       float* __restrict__ out, int N) {
    const float2* r = (insel == 1) ? (const float2*)g_rA : (const float2*)g_rB;
    const float* cf = &g_coef[2 * 128];
    int t   = threadIdx.x;  // 256
    int w   = t & 31;
    int sub = t >> 5;       // 0..7
    float a0 = cf[2 * w],      a1 = cf[2 * w + 1];
    float b0 = cf[64 + 2 * w], b1 = cf[65 + 2 * w];
    int n0  = blockIdx.x * 256;
    int nend = min(n0 + 256, N);
    float2 acc = make_float2(0.f, 0.f);
    int curg = -1;
    for (int n = n0 + sub; n < nend; n += 8) {
        int g = batch[n];
        if (g != curg) {
            if (curg >= 0) {
                atomicAdd(&out[curg * 64 + 2 * w],     acc.x);
                atomicAdd(&out[curg * 64 + 2 * w + 1], acc.y);
            }
            curg = g;
            acc = make_float2(0.f, 0.f);
        }
        float2 v = r[(size_t)n * 32 + w];
        acc.x += fmaf(a0, v.x, b0);
        acc.y += fmaf(a1, v.y, b1);
    }
    if (curg >= 0) {
        atomicAdd(&out[curg * 64 + 2 * w],     acc.x);
        atomicAdd(&out[curg * 64 + 2 * w + 1], acc.y);
    }
}

// ---------------------------- launch ----------------------------------------
extern "C" void kernel_launch(void* const* d_in, const int* in_sizes, int n_in,
                              void* d_out, int out_size) {
    const float* x     = (const float*)d_in[0];
    const int*   ei    = (const int*)d_in[1];
    const int*   batch = (const int*)d_in[2];

    const float* WA[3] = {(const float*)d_in[3],  (const float*)d_in[9],  (const float*)d_in[15]};
    const float* BA[3] = {(const float*)d_in[4],  (const float*)d_in[10], (const float*)d_in[16]};
    const float* WB[3] = {(const float*)d_in[5],  (const float*)d_in[11], (const float*)d_in[17]};
    const float* BB[3] = {(const float*)d_in[6],  (const float*)d_in[12], (const float*)d_in[18]};
    const float* GM[3] = {(const float*)d_in[7],  (const float*)d_in[13], (const float*)d_in[19]};
    const float* BE[3] = {(const float*)d_in[8],  (const float*)d_in[14], (const float*)d_in[20]};

    int N = in_sizes[0] / 64;
    int E = in_sizes[1] / 2;
    const int* src = ei;
    const int* dst = ei + E;

    const int DYN = 3 * 64 * KP2 * (int)sizeof(uint2);   // 55296 B
    cudaFuncSetAttribute(k_layer, cudaFuncAttributeMaxDynamicSharedMemorySize, DYN);
    cudaFuncSetAttribute(k_layer, cudaFuncAttributePreferredSharedMemoryCarveout, 100);

    // build: zero cursor/stats, ELL adjacency
    k_zero<<<(N + 255) / 256, 256>>>(N);
    k_fill<<<(E + 255) / 256, 256>>>(src, dst, E);

    // 3 fused GIN layers
    int grid = (N + 63) / 64;
    int insel = 0;  // x
    for (int L = 0; L < 3; L++) {
        int outsel = (L & 1) ? 2 : 1;  // L0->rA, L1->rB, L2->rA
        k_layer<<<grid, 256, DYN>>>(x, insel, L,
                                    WA[L], BA[L], WB[L], BB[L], outsel, N);
        k_bnfin<<<1, 64>>>(GM[L], BE[L], L, N);
        insel = outsel;
    }

    cudaMemsetAsync(d_out, 0, (size_t)out_size * sizeof(float));
    k_pool<<<(N + 255) / 256, 256>>>(insel, batch, (float*)d_out, N);
}

// round 13
// speedup vs baseline: 1.1326x; 1.1326x over previous
#include <cuda_runtime.h>
#include <cuda_bf16.h>
#include <cstdint>

// ---------------------------------------------------------------------------
// GIN encoder: 3 x (GINConv(sum-agg) -> MLP(64,relu,64) -> relu -> BN) -> add-pool
// Round 13 = round-11 base (262us best-structure) + two k_mlp fixes:
//   * TPB 4 -> 2: grid 391 -> 782, per-SM load imbalance 1.5x -> 1.2x
//     (round-11 ncu: grid-limited at 2.64 blocks/SM)
//   * double-buffered cp.async A-prefetch: next tile's stage overlaps the
//     current tile's GEMMs (wait_group 1)
// Round-12 lesson (3rd fusion failure) recorded: gather and MLP stay split.
//   * k_agg: fp32 float2 gather, ELL + shfl, BN affine folded, writes packed
//     bf16 (hi,lo) uint2 A-fragments (g_aggP)
//   * k_mlp: uint2 smem bf16x3 m16n8k16, W staged once / 2 tiles,
//     BN stats in registers; sorted-batch pool
// ---------------------------------------------------------------------------

#define MAXN 131072
#define ELLW 64
#define KP2  36                 // smem pitch in uint2 words
#define TPB  2                  // tiles (64 rows) per k_mlp block

__device__ int   g_cursor[MAXN];
__device__ int   g_ell[(size_t)MAXN * ELLW];
__device__ float g_rA[(size_t)MAXN * 64];
__device__ float g_rB[(size_t)MAXN * 64];
__device__ uint2 g_aggP[(size_t)MAXN * 32];   // packed bf16 (hi,lo) per k-pair
__device__ float g_stats[3 * 128];   // per layer: [0:64) sum, [64:128) sumsq
__device__ float g_coef[3 * 128];    // per layer: [0:64) scale a, [64:128) shift b

// split (ev,od) floats into packed-bf16 hi word (ev low half) + lo word
__device__ __forceinline__ void bf16split2(float ev, float od,
                                           uint32_t& hi, uint32_t& lo) {
    __nv_bfloat16 he = __float2bfloat16_rn(ev);
    __nv_bfloat16 ho = __float2bfloat16_rn(od);
    float le = ev - __bfloat162float(he);
    float lo_f = od - __bfloat162float(ho);
    __nv_bfloat162 ph, pl;
    ph.x = he; ph.y = ho;
    pl.x = __float2bfloat16_rn(le); pl.y = __float2bfloat16_rn(lo_f);
    hi = *(uint32_t*)&ph;
    lo = *(uint32_t*)&pl;
}

__device__ __forceinline__ void mma_bf16(float c[4],
    uint32_t a0, uint32_t a1, uint32_t a2, uint32_t a3,
    uint32_t b0, uint32_t b1)
{
    asm volatile(
        "mma.sync.aligned.m16n8k16.row.col.f32.bf16.bf16.f32 "
        "{%0,%1,%2,%3}, {%4,%5,%6,%7}, {%8,%9}, {%0,%1,%2,%3};"
        : "+f"(c[0]), "+f"(c[1]), "+f"(c[2]), "+f"(c[3])
        : "r"(a0), "r"(a1), "r"(a2), "r"(a3), "r"(b0), "r"(b1));
}

__device__ __forceinline__ void cp_async16(void* sdst, const void* gsrc) {
    uint32_t s = (uint32_t)__cvta_generic_to_shared(sdst);
    asm volatile("cp.async.cg.shared.global [%0], [%1], 16;" :: "r"(s), "l"(gsrc));
}

// ---------------------------- build ----------------------------------------

__global__ void k_zero(int N) {
    int i = blockIdx.x * blockDim.x + threadIdx.x;
    if (i < N)   g_cursor[i] = 0;
    if (i < 384) g_stats[i]  = 0.f;
}

__global__ void k_fill(const int* __restrict__ src, const int* __restrict__ dst, int E) {
    int e = blockIdx.x * blockDim.x + threadIdx.x;
    if (e < E) {
        int d = dst[e];
        int p = atomicAdd(&g_cursor[d], 1);
        if (p < ELLW) g_ell[(size_t)d * ELLW + p] = src[e];
    }
}

// ---------------------------- aggregation -----------------------------------
// 1 warp/node, float2/lane, ELL indices via coalesced load + shfl.
// Prev layer BN affine folded in; output = packed bf16 (hi,lo) A-tile words.
__global__ __launch_bounds__(256) void k_agg(
    const float* __restrict__ x, int insel /*0=x,1=rA,2=rB*/, int layer, int N)
{
    int gt   = blockIdx.x * blockDim.x + threadIdx.x;
    int node = gt >> 5;
    int lane = gt & 31;
    if (node >= N) return;

    const float2* __restrict__ inp =
        (insel == 0) ? (const float2*)x :
        (insel == 1) ? (const float2*)g_rA : (const float2*)g_rB;

    float2 acc = inp[(size_t)node * 32 + lane];   // self term
    int deg = min(g_cursor[node], ELLW);
    const int* cols = g_ell + (size_t)node * ELLW;
    int c0 = cols[lane];
    int c1 = cols[lane + 32];

    int d0 = min(deg, 32);
    int e = 0;
    for (; e + 3 < d0; e += 4) {
        int s0 = __shfl_sync(0xffffffffu, c0, e);
        int s1 = __shfl_sync(0xffffffffu, c0, e + 1);
        int s2 = __shfl_sync(0xffffffffu, c0, e + 2);
        int s3 = __shfl_sync(0xffffffffu, c0, e + 3);
        float2 v0 = inp[(size_t)s0 * 32 + lane];
        float2 v1 = inp[(size_t)s1 * 32 + lane];
        float2 v2 = inp[(size_t)s2 * 32 + lane];
        float2 v3 = inp[(size_t)s3 * 32 + lane];
        acc.x += (v0.x + v1.x) + (v2.x + v3.x);
        acc.y += (v0.y + v1.y) + (v2.y + v3.y);
    }
    for (; e < d0; e++) {
        int s = __shfl_sync(0xffffffffu, c0, e);
        float2 v = inp[(size_t)s * 32 + lane];
        acc.x += v.x;
        acc.y += v.y;
    }
    int d1 = deg - 32;
    for (int e2 = 0; e2 < d1; e2++) {
        int s = __shfl_sync(0xffffffffu, c1, e2);
        float2 v = inp[(size_t)s * 32 + lane];
        acc.x += v.x;
        acc.y += v.y;
    }

    if (layer > 0) {
        const float* cf = &g_coef[(layer - 1) * 128];
        float a0 = cf[2 * lane],      a1 = cf[2 * lane + 1];
        float b0 = cf[64 + 2 * lane], b1 = cf[65 + 2 * lane];
        float cnt = (float)(deg + 1);
        acc.x = a0 * acc.x + cnt * b0;
        acc.y = a1 * acc.y + cnt * b1;
    }
    uint32_t hi, lo;
    bf16split2(acc.x, acc.y, hi, lo);
    g_aggP[(size_t)node * 32 + lane] = make_uint2(hi, lo);
}

// ---------------- bf16x3 tensor-core MLP, double-buffered cp.async ----------
// 256 threads (8 warps), TPB tiles of 64 rows. Warp tile m16 x n32.
// dyn smem: Q1 (W1, [n][kp]), Q2 (W2), P[2] (A / h, double-buffered).
__global__ __launch_bounds__(256) void k_mlp(
    const float* __restrict__ wa, const float* __restrict__ ba,
    const float* __restrict__ wb, const float* __restrict__ bb,
    int outsel /*1=rA,2=rB*/, int layer, int N)
{
    extern __shared__ uint2 dyn[];
    uint2* Q1 = dyn;
    uint2* Q2 = dyn + 64 * KP2;
    uint2* P0 = dyn + 2 * 64 * KP2;
    uint2* P1 = dyn + 3 * 64 * KP2;
    __shared__ float B1s[64], B2s[64];
    __shared__ float ssum[64], ssq[64];

    float* rout = (outsel == 1) ? g_rA : g_rB;
    int t    = threadIdx.x;
    int lane = t & 31, warp = t >> 5;
    int gid  = lane >> 2, tig = lane & 3;
    int mi   = warp & 3,  ni  = warp >> 2;

    // stage W1 + W2 once per block
#pragma unroll
    for (int i = 0; i < 8; i++) {
        int idx = t + 256 * i;        // 0..2047
        int n = idx & 63, kp = idx >> 6;
        uint32_t hi, lo;
        bf16split2(wa[(2 * kp) * 64 + n], wa[(2 * kp + 1) * 64 + n], hi, lo);
        Q1[n * KP2 + kp] = make_uint2(hi, lo);
        bf16split2(wb[(2 * kp) * 64 + n], wb[(2 * kp + 1) * 64 + n], hi, lo);
        Q2[n * KP2 + kp] = make_uint2(hi, lo);
    }
    if (t < 64) { B1s[t] = ba[t]; B2s[t] = bb[t]; ssum[t] = 0.f; ssq[t] = 0.f; }

    int tile0 = blockIdx.x * TPB;

    // prefetch tile 0 into P0
    {
        int m0 = tile0 * 64;
#pragma unroll
        for (int j = 0; j < 4; j++) {
            int idx = t + 256 * j;
            int row = idx >> 4;
            int cp  = (idx & 15) * 2;
            cp_async16(&P0[row * KP2 + cp], &g_aggP[(size_t)(m0 + row) * 32 + cp]);
        }
        asm volatile("cp.async.commit_group;");
    }

    int aoff = (mi * 16 + gid) * KP2 + tig;
    int boff = (ni * 32 + gid) * KP2 + tig;

    // per-thread BN-stat accumulators across tiles
    float ts[8], tq[8];
#pragma unroll
    for (int i = 0; i < 8; i++) { ts[i] = 0.f; tq[i] = 0.f; }

#pragma unroll 1
    for (int tile = 0; tile < TPB; tile++) {
        int m0 = (tile0 + tile) * 64;
        if (m0 >= N) break;
        uint2* P = (tile & 1) ? P1 : P0;

        // prefetch next tile into the other buffer, then wait for current
        bool pf = (tile + 1 < TPB) && ((tile0 + tile + 1) * 64 < N);
        if (pf) {
            uint2* Pn = (tile & 1) ? P0 : P1;
            int mn = (tile0 + tile + 1) * 64;
#pragma unroll
            for (int j = 0; j < 4; j++) {
                int idx = t + 256 * j;
                int row = idx >> 4;
                int cp  = (idx & 15) * 2;
                cp_async16(&Pn[row * KP2 + cp], &g_aggP[(size_t)(mn + row) * 32 + cp]);
            }
            asm volatile("cp.async.commit_group;");
            asm volatile("cp.async.wait_group 1;" ::: "memory");
        } else {
            asm volatile("cp.async.wait_group 0;" ::: "memory");
        }
        __syncthreads();

        float c[4][4];
#pragma unroll
        for (int nt = 0; nt < 4; nt++)
#pragma unroll
            for (int i = 0; i < 4; i++) c[nt][i] = 0.f;

        // GEMM1
#pragma unroll
        for (int kt = 0; kt < 4; kt++) {
            uint2 a0 = P[aoff + kt * 8];
            uint2 a1 = P[aoff + kt * 8 + 8 * KP2];
            uint2 a2 = P[aoff + kt * 8 + 4];
            uint2 a3 = P[aoff + kt * 8 + 8 * KP2 + 4];
#pragma unroll
            for (int nt = 0; nt < 4; nt++) {
                uint2 b0 = Q1[boff + nt * 8 * KP2 + kt * 8];
                uint2 b1 = Q1[boff + nt * 8 * KP2 + kt * 8 + 4];
                mma_bf16(c[nt], a0.x, a1.x, a2.x, a3.x, b0.x, b1.x);
                mma_bf16(c[nt], a0.x, a1.x, a2.x, a3.x, b0.y, b1.y);
                mma_bf16(c[nt], a0.y, a1.y, a2.y, a3.y, b0.x, b1.x);
            }
        }
        __syncthreads();   // all P reads (A) done

        // h = relu(c + b1) -> P
#pragma unroll
        for (int nt = 0; nt < 4; nt++) {
            int n0 = ni * 32 + nt * 8 + 2 * tig;
            float bb0 = B1s[n0], bb1 = B1s[n0 + 1];
            int r0 = mi * 16 + gid;
            int kp = n0 >> 1;
            uint32_t hi, lo;
            bf16split2(fmaxf(c[nt][0] + bb0, 0.f), fmaxf(c[nt][1] + bb1, 0.f), hi, lo);
            P[r0 * KP2 + kp] = make_uint2(hi, lo);
            bf16split2(fmaxf(c[nt][2] + bb0, 0.f), fmaxf(c[nt][3] + bb1, 0.f), hi, lo);
            P[(r0 + 8) * KP2 + kp] = make_uint2(hi, lo);
#pragma unroll
            for (int i = 0; i < 4; i++) c[nt][i] = 0.f;
        }
        __syncthreads();

        // GEMM2
#pragma unroll
        for (int kt = 0; kt < 4; kt++) {
            uint2 a0 = P[aoff + kt * 8];
            uint2 a1 = P[aoff + kt * 8 + 8 * KP2];
            uint2 a2 = P[aoff + kt * 8 + 4];
            uint2 a3 = P[aoff + kt * 8 + 8 * KP2 + 4];
#pragma unroll
            for (int nt = 0; nt < 4; nt++) {
                uint2 b0 = Q2[boff + nt * 8 * KP2 + kt * 8];
                uint2 b1 = Q2[boff + nt * 8 * KP2 + kt * 8 + 4];
                mma_bf16(c[nt], a0.x, a1.x, a2.x, a3.x, b0.x, b1.x);
                mma_bf16(c[nt], a0.x, a1.x, a2.x, a3.x, b0.y, b1.y);
                mma_bf16(c[nt], a0.y, a1.y, a2.y, a3.y, b0.x, b1.x);
            }
        }

        // epilogue: relu + bias2, store fp32, accumulate BN stats in registers
        int gr0 = m0 + mi * 16 + gid, gr1 = gr0 + 8;
        bool ok0 = gr0 < N, ok1 = gr1 < N;
#pragma unroll
        for (int nt = 0; nt < 4; nt++) {
            int n0 = ni * 32 + nt * 8 + 2 * tig;
            float bb0 = B2s[n0], bb1 = B2s[n0 + 1];
            float v00 = fmaxf(c[nt][0] + bb0, 0.f);
            float v01 = fmaxf(c[nt][1] + bb1, 0.f);
            float v10 = fmaxf(c[nt][2] + bb0, 0.f);
            float v11 = fmaxf(c[nt][3] + bb1, 0.f);
            if (ok0) {
                *(float2*)&rout[(size_t)gr0 * 64 + n0] = make_float2(v00, v01);
                ts[2 * nt]     += v00; tq[2 * nt]     += v00 * v00;
                ts[2 * nt + 1] += v01; tq[2 * nt + 1] += v01 * v01;
            }
            if (ok1) {
                *(float2*)&rout[(size_t)gr1 * 64 + n0] = make_float2(v10, v11);
                ts[2 * nt]     += v10; tq[2 * nt]     += v10 * v10;
                ts[2 * nt + 1] += v11; tq[2 * nt + 1] += v11 * v11;
            }
        }
        __syncthreads();   // P reads done before this buffer is re-used
    }

    // one smem-atomic stats pass per block, then global flush
#pragma unroll
    for (int nt = 0; nt < 4; nt++) {
        int n0 = ni * 32 + nt * 8 + 2 * tig;
        atomicAdd(&ssum[n0],     ts[2 * nt]);
        atomicAdd(&ssq[n0],      tq[2 * nt]);
        atomicAdd(&ssum[n0 + 1], ts[2 * nt + 1]);
        atomicAdd(&ssq[n0 + 1],  tq[2 * nt + 1]);
    }
    __syncthreads();
    if (t < 64) {
        atomicAdd(&g_stats[layer * 128 + t],      ssum[t]);
        atomicAdd(&g_stats[layer * 128 + 64 + t], ssq[t]);
    }
}

// ---------------------------- BN finalize -----------------------------------
__global__ void k_bnfin(const float* __restrict__ gamma,
                        const float* __restrict__ beta, int layer, int N) {
    int t = threadIdx.x;  // 64
    if (t >= 64) return;
    float invN = 1.f / (float)N;
    float mean = g_stats[layer * 128 + t] * invN;
    float var  = g_stats[layer * 128 + 64 + t] * invN - mean * mean;
    var = fmaxf(var, 0.f);
    float s = gamma[t] * rsqrtf(var + 1e-5f);
    g_coef[layer * 128 + t]      = s;
    g_coef[layer * 128 + 64 + t] = beta[t] - mean * s;
}

// ---------------------------- pool ------------------------------------------
// batch sorted: run-length accumulate, atomics only at graph boundaries.
__global__ void k_pool(int insel /*1=rA,2=rB*/, const int* __restrict__ batch,
                       float* __restrict__ out, int N) {
    const float2* r = (insel == 1) ? (const float2*)g_rA : (const float2*)g_rB;
    const float* cf = &g_coef[2 * 128];
    int t   = threadIdx.x;  // 256
    int w   = t & 31;
    int sub = t >> 5;       // 0..7
    float a0 = cf[2 * w],      a1 = cf[2 * w + 1];
    float b0 = cf[64 + 2 * w], b1 = cf[65 + 2 * w];
    int n0  = blockIdx.x * 256;
    int nend = min(n0 + 256, N);
    float2 acc = make_float2(0.f, 0.f);
    int curg = -1;
    for (int n = n0 + sub; n < nend; n += 8) {
        int g = batch[n];
        if (g != curg) {
            if (curg >= 0) {
                atomicAdd(&out[curg * 64 + 2 * w],     acc.x);
                atomicAdd(&out[curg * 64 + 2 * w + 1], acc.y);
            }
            curg = g;
            acc = make_float2(0.f, 0.f);
        }
        float2 v = r[(size_t)n * 32 + w];
        acc.x += fmaf(a0, v.x, b0);
        acc.y += fmaf(a1, v.y, b1);
    }
    if (curg >= 0) {
        atomicAdd(&out[curg * 64 + 2 * w],     acc.x);
        atomicAdd(&out[curg * 64 + 2 * w + 1], acc.y);
    }
}

// ---------------------------- launch ----------------------------------------
extern "C" void kernel_launch(void* const* d_in, const int* in_sizes, int n_in,
                              void* d_out, int out_size) {
    const float* x     = (const float*)d_in[0];
    const int*   ei    = (const int*)d_in[1];
    const int*   batch = (const int*)d_in[2];

    const float* WA[3] = {(const float*)d_in[3],  (const float*)d_in[9],  (const float*)d_in[15]};
    const float* BA[3] = {(const float*)d_in[4],  (const float*)d_in[10], (const float*)d_in[16]};
    const float* WB[3] = {(const float*)d_in[5],  (const float*)d_in[11], (const float*)d_in[17]};
    const float* BB[3] = {(const float*)d_in[6],  (const float*)d_in[12], (const float*)d_in[18]};
    const float* GM[3] = {(const float*)d_in[7],  (const float*)d_in[13], (const float*)d_in[19]};
    const float* BE[3] = {(const float*)d_in[8],  (const float*)d_in[14], (const float*)d_in[20]};

    int N = in_sizes[0] / 64;
    int E = in_sizes[1] / 2;
    const int* src = ei;
    const int* dst = ei + E;

    const int DYN = 4 * 64 * KP2 * (int)sizeof(uint2);   // 73728 B
    cudaFuncSetAttribute(k_mlp, cudaFuncAttributeMaxDynamicSharedMemorySize, DYN);
    cudaFuncSetAttribute(k_mlp, cudaFuncAttributePreferredSharedMemoryCarveout, 100);

    // build: zero cursor/stats, ELL adjacency
    k_zero<<<(N + 255) / 256, 256>>>(N);
    k_fill<<<(E + 255) / 256, 256>>>(src, dst, E);

    // 3 GIN layers
    int ntile = (N + 63) / 64;
    int mgrid = (ntile + TPB - 1) / TPB;
    int insel = 0;  // x
    for (int L = 0; L < 3; L++) {
        int outsel = (L & 1) ? 2 : 1;  // L0->rA, L1->rB, L2->rA
        k_agg<<<((size_t)N * 32 + 255) / 256, 256>>>(x, insel, L, N);
        k_mlp<<<mgrid, 256, DYN>>>(WA[L], BA[L], WB[L], BB[L], outsel, L, N);
        k_bnfin<<<1, 64>>>(GM[L], BE[L], L, N);
        insel = outsel;
    }

    cudaMemsetAsync(d_out, 0, (size_t)out_size * sizeof(float));
    k_pool<<<(N + 255) / 256, 256>>>(insel, batch, (float*)d_out, N);
}

// round 14
// speedup vs baseline: 1.4015x; 1.2375x over previous
#include <cuda_runtime.h>
#include <cuda_bf16.h>
#include <cstdint>

// ---------------------------------------------------------------------------
// GIN encoder: 3 x (GINConv(sum-agg) -> MLP(64,relu,64) -> relu -> BN) -> add-pool
// Round 14 = round-11 base (262us best) + two zero-register-cost changes:
//   * k_mlp: persistent grid-stride, 444 blocks = 148 SMs x 3 -> every SM
//     carries exactly 3 blocks (round-11 was 391 blocks: 95 SMs x3 / 53 x2,
//     a 1.5x wave imbalance). Round-13 lesson: regs must stay <= 80 -> the
//     loop structure is unchanged, only the tile indexing.
//   * k_bnfin deleted (3 x 4.4us launch tails): BN affine coefs computed
//     inline in k_agg / k_pool from g_stats + gamma/beta (identical math).
// Everything else identical to round 11:
//   * k_agg: fp32 float2 gather, ELL + shfl, writes packed bf16 (hi,lo)
//   * k_mlp: uint2 smem bf16x3 m16n8k16, W staged once per block, cp.async A,
//     BN stats in registers; sorted-batch pool. Fusion banned (3 failures).
// ---------------------------------------------------------------------------

#define MAXN 131072
#define ELLW 64
#define KP2  36                 // smem pitch in uint2 words

__device__ int   g_cursor[MAXN];
__device__ int   g_ell[(size_t)MAXN * ELLW];
__device__ float g_rA[(size_t)MAXN * 64];
__device__ float g_rB[(size_t)MAXN * 64];
__device__ uint2 g_aggP[(size_t)MAXN * 32];   // packed bf16 (hi,lo) per k-pair
__device__ float g_stats[3 * 128];   // per layer: [0:64) sum, [64:128) sumsq

// split (ev,od) floats into packed-bf16 hi word (ev low half) + lo word
__device__ __forceinline__ void bf16split2(float ev, float od,
                                           uint32_t& hi, uint32_t& lo) {
    __nv_bfloat16 he = __float2bfloat16_rn(ev);
    __nv_bfloat16 ho = __float2bfloat16_rn(od);
    float le = ev - __bfloat162float(he);
    float lo_f = od - __bfloat162float(ho);
    __nv_bfloat162 ph, pl;
    ph.x = he; ph.y = ho;
    pl.x = __float2bfloat16_rn(le); pl.y = __float2bfloat16_rn(lo_f);
    hi = *(uint32_t*)&ph;
    lo = *(uint32_t*)&pl;
}

__device__ __forceinline__ void mma_bf16(float c[4],
    uint32_t a0, uint32_t a1, uint32_t a2, uint32_t a3,
    uint32_t b0, uint32_t b1)
{
    asm volatile(
        "mma.sync.aligned.m16n8k16.row.col.f32.bf16.bf16.f32 "
        "{%0,%1,%2,%3}, {%4,%5,%6,%7}, {%8,%9}, {%0,%1,%2,%3};"
        : "+f"(c[0]), "+f"(c[1]), "+f"(c[2]), "+f"(c[3])
        : "r"(a0), "r"(a1), "r"(a2), "r"(a3), "r"(b0), "r"(b1));
}

__device__ __forceinline__ void cp_async16(void* sdst, const void* gsrc) {
    uint32_t s = (uint32_t)__cvta_generic_to_shared(sdst);
    asm volatile("cp.async.cg.shared.global [%0], [%1], 16;" :: "r"(s), "l"(gsrc));
}

// BN affine for feature f of layer l: out = a*h + b
__device__ __forceinline__ void bn_coef(const float* __restrict__ gamma,
                                        const float* __restrict__ beta,
                                        int layer, int f, float invN,
                                        float& a, float& b) {
    const float* st = &g_stats[layer * 128];
    float mean = st[f] * invN;
    float var  = fmaxf(st[64 + f] * invN - mean * mean, 0.f);
    a = gamma[f] * rsqrtf(var + 1e-5f);
    b = beta[f] - mean * a;
}

// ---------------------------- build ----------------------------------------

__global__ void k_zero(int N) {
    int i = blockIdx.x * blockDim.x + threadIdx.x;
    if (i < N)   g_cursor[i] = 0;
    if (i < 384) g_stats[i]  = 0.f;
}

__global__ void k_fill(const int* __restrict__ src, const int* __restrict__ dst, int E) {
    int e = blockIdx.x * blockDim.x + threadIdx.x;
    if (e < E) {
        int d = dst[e];
        int p = atomicAdd(&g_cursor[d], 1);
        if (p < ELLW) g_ell[(size_t)d * ELLW + p] = src[e];
    }
}

// ---------------------------- aggregation -----------------------------------
// 1 warp/node, float2/lane, ELL indices via coalesced load + shfl.
// Prev-layer BN affine computed inline from g_stats (no k_bnfin kernel).
__global__ __launch_bounds__(256) void k_agg(
    const float* __restrict__ x, int insel /*0=x,1=rA,2=rB*/, int layer,
    const float* __restrict__ gamma, const float* __restrict__ beta, int N)
{
    int gt   = blockIdx.x * blockDim.x + threadIdx.x;
    int node = gt >> 5;
    int lane = gt & 31;
    if (node >= N) return;

    const float2* __restrict__ inp =
        (insel == 0) ? (const float2*)x :
        (insel == 1) ? (const float2*)g_rA : (const float2*)g_rB;

    float a0c = 1.f, a1c = 1.f, b0c = 0.f, b1c = 0.f;
    if (layer > 0) {
        float invN = 1.f / (float)N;
        bn_coef(gamma, beta, layer - 1, 2 * lane,     invN, a0c, b0c);
        bn_coef(gamma, beta, layer - 1, 2 * lane + 1, invN, a1c, b1c);
    }

    float2 acc = inp[(size_t)node * 32 + lane];   // self term
    int deg = min(g_cursor[node], ELLW);
    const int* cols = g_ell + (size_t)node * ELLW;
    int c0 = cols[lane];
    int c1 = cols[lane + 32];

    int d0 = min(deg, 32);
    int e = 0;
    for (; e + 3 < d0; e += 4) {
        int s0 = __shfl_sync(0xffffffffu, c0, e);
        int s1 = __shfl_sync(0xffffffffu, c0, e + 1);
        int s2 = __shfl_sync(0xffffffffu, c0, e + 2);
        int s3 = __shfl_sync(0xffffffffu, c0, e + 3);
        float2 v0 = inp[(size_t)s0 * 32 + lane];
        float2 v1 = inp[(size_t)s1 * 32 + lane];
        float2 v2 = inp[(size_t)s2 * 32 + lane];
        float2 v3 = inp[(size_t)s3 * 32 + lane];
        acc.x += (v0.x + v1.x) + (v2.x + v3.x);
        acc.y += (v0.y + v1.y) + (v2.y + v3.y);
    }
    for (; e < d0; e++) {
        int s = __shfl_sync(0xffffffffu, c0, e);
        float2 v = inp[(size_t)s * 32 + lane];
        acc.x += v.x;
        acc.y += v.y;
    }
    int d1 = deg - 32;
    for (int e2 = 0; e2 < d1; e2++) {
        int s = __shfl_sync(0xffffffffu, c1, e2);
        float2 v = inp[(size_t)s * 32 + lane];
        acc.x += v.x;
        acc.y += v.y;
    }

    if (layer > 0) {
        float cnt = (float)(deg + 1);
        acc.x = a0c * acc.x + cnt * b0c;
        acc.y = a1c * acc.y + cnt * b1c;
    }
    uint32_t hi, lo;
    bf16split2(acc.x, acc.y, hi, lo);
    g_aggP[(size_t)node * 32 + lane] = make_uint2(hi, lo);
}

// ---------------- bf16x3 tensor-core MLP, persistent grid-stride ------------
// 256 threads (8 warps), 444 blocks (3/SM exactly). Warp tile m16 x n32.
// dyn smem: Q1 (W1, [n][kp]), Q2 (W2), P (A / h).
__global__ __launch_bounds__(256) void k_mlp(
    const float* __restrict__ wa, const float* __restrict__ ba,
    const float* __restrict__ wb, const float* __restrict__ bb,
    int outsel /*1=rA,2=rB*/, int layer, int N)
{
    extern __shared__ uint2 dyn[];
    uint2* Q1 = dyn;
    uint2* Q2 = dyn + 64 * KP2;
    uint2* P  = dyn + 2 * 64 * KP2;
    __shared__ float B1s[64], B2s[64];
    __shared__ float ssum[64], ssq[64];

    float* rout = (outsel == 1) ? g_rA : g_rB;
    int t    = threadIdx.x;
    int lane = t & 31, warp = t >> 5;
    int gid  = lane >> 2, tig = lane & 3;
    int mi   = warp & 3,  ni  = warp >> 2;

    // stage W1 + W2 once per block
#pragma unroll
    for (int i = 0; i < 8; i++) {
        int idx = t + 256 * i;        // 0..2047
        int n = idx & 63, kp = idx >> 6;
        uint32_t hi, lo;
        bf16split2(wa[(2 * kp) * 64 + n], wa[(2 * kp + 1) * 64 + n], hi, lo);
        Q1[n * KP2 + kp] = make_uint2(hi, lo);
        bf16split2(wb[(2 * kp) * 64 + n], wb[(2 * kp + 1) * 64 + n], hi, lo);
        Q2[n * KP2 + kp] = make_uint2(hi, lo);
    }
    if (t < 64) { B1s[t] = ba[t]; B2s[t] = bb[t]; ssum[t] = 0.f; ssq[t] = 0.f; }
    __syncthreads();

    int aoff = (mi * 16 + gid) * KP2 + tig;
    int boff = (ni * 32 + gid) * KP2 + tig;

    // per-thread BN-stat accumulators across tiles
    float ts[8], tq[8];
#pragma unroll
    for (int i = 0; i < 8; i++) { ts[i] = 0.f; tq[i] = 0.f; }

    int ntile = (N + 63) >> 6;
#pragma unroll 1
    for (int tile = blockIdx.x; tile < ntile; tile += gridDim.x) {
        int m0 = tile * 64;

        // stage A tile via cp.async: 1024 16B chunks (2 uint2 each)
#pragma unroll
        for (int j = 0; j < 4; j++) {
            int idx = t + 256 * j;         // 0..1023
            int row = idx >> 4;
            int cp  = (idx & 15) * 2;      // uint2 pair index
            cp_async16(&P[row * KP2 + cp], &g_aggP[(size_t)(m0 + row) * 32 + cp]);
        }
        asm volatile("cp.async.commit_group;");
        asm volatile("cp.async.wait_group 0;" ::: "memory");
        __syncthreads();

        float c[4][4];
#pragma unroll
        for (int nt = 0; nt < 4; nt++)
#pragma unroll
            for (int i = 0; i < 4; i++) c[nt][i] = 0.f;

        // GEMM1
#pragma unroll
        for (int kt = 0; kt < 4; kt++) {
            uint2 a0 = P[aoff + kt * 8];
            uint2 a1 = P[aoff + kt * 8 + 8 * KP2];
            uint2 a2 = P[aoff + kt * 8 + 4];
            uint2 a3 = P[aoff + kt * 8 + 8 * KP2 + 4];
#pragma unroll
            for (int nt = 0; nt < 4; nt++) {
                uint2 b0 = Q1[boff + nt * 8 * KP2 + kt * 8];
                uint2 b1 = Q1[boff + nt * 8 * KP2 + kt * 8 + 4];
                mma_bf16(c[nt], a0.x, a1.x, a2.x, a3.x, b0.x, b1.x);
                mma_bf16(c[nt], a0.x, a1.x, a2.x, a3.x, b0.y, b1.y);
                mma_bf16(c[nt], a0.y, a1.y, a2.y, a3.y, b0.x, b1.x);
            }
        }
        __syncthreads();   // all P reads (A) done

        // h = relu(c + b1) -> P
#pragma unroll
        for (int nt = 0; nt < 4; nt++) {
            int n0 = ni * 32 + nt * 8 + 2 * tig;
            float bb0 = B1s[n0], bb1 = B1s[n0 + 1];
            int r0 = mi * 16 + gid;
            int kp = n0 >> 1;
            uint32_t hi, lo;
            bf16split2(fmaxf(c[nt][0] + bb0, 0.f), fmaxf(c[nt][1] + bb1, 0.f), hi, lo);
            P[r0 * KP2 + kp] = make_uint2(hi, lo);
            bf16split2(fmaxf(c[nt][2] + bb0, 0.f), fmaxf(c[nt][3] + bb1, 0.f), hi, lo);
            P[(r0 + 8) * KP2 + kp] = make_uint2(hi, lo);
#pragma unroll
            for (int i = 0; i < 4; i++) c[nt][i] = 0.f;
        }
        __syncthreads();

        // GEMM2
#pragma unroll
        for (int kt = 0; kt < 4; kt++) {
            uint2 a0 = P[aoff + kt * 8];
            uint2 a1 = P[aoff + kt * 8 + 8 * KP2];
            uint2 a2 = P[aoff + kt * 8 + 4];
            uint2 a3 = P[aoff + kt * 8 + 8 * KP2 + 4];
#pragma unroll
            for (int nt = 0; nt < 4; nt++) {
                uint2 b0 = Q2[boff + nt * 8 * KP2 + kt * 8];
                uint2 b1 = Q2[boff + nt * 8 * KP2 + kt * 8 + 4];
                mma_bf16(c[nt], a0.x, a1.x, a2.x, a3.x, b0.x, b1.x);
                mma_bf16(c[nt], a0.x, a1.x, a2.x, a3.x, b0.y, b1.y);
                mma_bf16(c[nt], a0.y, a1.y, a2.y, a3.y, b0.x, b1.x);
            }
        }

        // epilogue: relu + bias2, store fp32, accumulate BN stats in registers
        int gr0 = m0 + mi * 16 + gid, gr1 = gr0 + 8;
        bool ok0 = gr0 < N, ok1 = gr1 < N;
#pragma unroll
        for (int nt = 0; nt < 4; nt++) {
            int n0 = ni * 32 + nt * 8 + 2 * tig;
            float bb0 = B2s[n0], bb1 = B2s[n0 + 1];
            float v00 = fmaxf(c[nt][0] + bb0, 0.f);
            float v01 = fmaxf(c[nt][1] + bb1, 0.f);
            float v10 = fmaxf(c[nt][2] + bb0, 0.f);
            float v11 = fmaxf(c[nt][3] + bb1, 0.f);
            if (ok0) {
                *(float2*)&rout[(size_t)gr0 * 64 + n0] = make_float2(v00, v01);
                ts[2 * nt]     += v00; tq[2 * nt]     += v00 * v00;
                ts[2 * nt + 1] += v01; tq[2 * nt + 1] += v01 * v01;
            }
            if (ok1) {
                *(float2*)&rout[(size_t)gr1 * 64 + n0] = make_float2(v10, v11);
                ts[2 * nt]     += v10; tq[2 * nt]     += v10 * v10;
                ts[2 * nt + 1] += v11; tq[2 * nt + 1] += v11 * v11;
            }
        }
        __syncthreads();   // P reads done before next tile restages
    }

    // one smem-atomic stats pass per block, then global flush
#pragma unroll
    for (int nt = 0; nt < 4; nt++) {
        int n0 = ni * 32 + nt * 8 + 2 * tig;
        atomicAdd(&ssum[n0],     ts[2 * nt]);
        atomicAdd(&ssq[n0],      tq[2 * nt]);
        atomicAdd(&ssum[n0 + 1], ts[2 * nt + 1]);
        atomicAdd(&ssq[n0 + 1],  tq[2 * nt + 1]);
    }
    __syncthreads();
    if (t < 64) {
        atomicAdd(&g_stats[layer * 128 + t],      ssum[t]);
        atomicAdd(&g_stats[layer * 128 + 64 + t], ssq[t]);
    }
}

// ---------------------------- pool ------------------------------------------
// batch sorted: run-length accumulate, atomics only at graph boundaries.
// Layer-3 BN affine computed inline from g_stats.
__global__ void k_pool(int insel /*1=rA,2=rB*/, const int* __restrict__ batch,
                       const float* __restrict__ gamma, const float* __restrict__ beta,
                       float* __restrict__ out, int N) {
    const float2* r = (insel == 1) ? (const float2*)g_rA : (const float2*)g_rB;
    int t   = threadIdx.x;  // 256
    int w   = t & 31;
    int sub = t >> 5;       // 0..7
    float invN = 1.f / (float)N;
    float a0, b0, a1, b1;
    bn_coef(gamma, beta, 2, 2 * w,     invN, a0, b0);
    bn_coef(gamma, beta, 2, 2 * w + 1, invN, a1, b1);
    int n0  = blockIdx.x * 256;
    int nend = min(n0 + 256, N);
    float2 acc = make_float2(0.f, 0.f);
    int curg = -1;
    for (int n = n0 + sub; n < nend; n += 8) {
        int g = batch[n];
        if (g != curg) {
            if (curg >= 0) {
                atomicAdd(&out[curg * 64 + 2 * w],     acc.x);
                atomicAdd(&out[curg * 64 + 2 * w + 1], acc.y);
            }
            curg = g;
            acc = make_float2(0.f, 0.f);
        }
        float2 v = r[(size_t)n * 32 + w];
        acc.x += fmaf(a0, v.x, b0);
        acc.y += fmaf(a1, v.y, b1);
    }
    if (curg >= 0) {
        atomicAdd(&out[curg * 64 + 2 * w],     acc.x);
        atomicAdd(&out[curg * 64 + 2 * w + 1], acc.y);
    }
}

// ---------------------------- launch ----------------------------------------
extern "C" void kernel_launch(void* const* d_in, const int* in_sizes, int n_in,
                              void* d_out, int out_size) {
    const float* x     = (const float*)d_in[0];
    const int*   ei    = (const int*)d_in[1];
    const int*   batch = (const int*)d_in[2];

    const float* WA[3] = {(const float*)d_in[3],  (const float*)d_in[9],  (const float*)d_in[15]};
    const float* BA[3] = {(const float*)d_in[4],  (const float*)d_in[10], (const float*)d_in[16]};
    const float* WB[3] = {(const float*)d_in[5],  (const float*)d_in[11], (const float*)d_in[17]};
    const float* BB[3] = {(const float*)d_in[6],  (const float*)d_in[12], (const float*)d_in[18]};
    const float* GM[3] = {(const float*)d_in[7],  (const float*)d_in[13], (const float*)d_in[19]};
    const float* BE[3] = {(const float*)d_in[8],  (const float*)d_in[14], (const float*)d_in[20]};

    int N = in_sizes[0] / 64;
    int E = in_sizes[1] / 2;
    const int* src = ei;
    const int* dst = ei + E;

    const int DYN = 3 * 64 * KP2 * (int)sizeof(uint2);   // 55296 B
    cudaFuncSetAttribute(k_mlp, cudaFuncAttributeMaxDynamicSharedMemorySize, DYN);
    cudaFuncSetAttribute(k_mlp, cudaFuncAttributePreferredSharedMemoryCarveout, 100);

    // build: zero cursor/stats, ELL adjacency
    k_zero<<<(N + 255) / 256, 256>>>(N);
    k_fill<<<(E + 255) / 256, 256>>>(src, dst, E);

    // 3 GIN layers (no k_bnfin; BN coefs inline in consumers)
    int ntile = (N + 63) / 64;
    int mgrid = 444 < ntile ? 444 : ntile;   // 148 SMs x 3 blocks
    int insel = 0;  // x
    for (int L = 0; L < 3; L++) {
        int outsel = (L & 1) ? 2 : 1;  // L0->rA, L1->rB, L2->rA
        const float* pg = (L > 0) ? GM[L - 1] : GM[0];
        const float* pb = (L > 0) ? BE[L - 1] : BE[0];
        k_agg<<<((size_t)N * 32 + 255) / 256, 256>>>(x, insel, L, pg, pb, N);
        k_mlp<<<mgrid, 256, DYN>>>(WA[L], BA[L], WB[L], BB[L], outsel, L, N);
        insel = outsel;
    }

    cudaMemsetAsync(d_out, 0, (size_t)out_size * sizeof(float));
    k_pool<<<(N + 255) / 256, 256>>>(insel, batch, GM[2], BE[2], (float*)d_out, N);
}